// round 16
// baseline (speedup 1.0000x reference)
#include <cuda_runtime.h>
#include <cuda_fp16.h>
#include <math.h>

#define BB 4
#define SS_ 8192
#define DD 2048
#define HH 16
#define DKV 128
#define DHID 8192
#define SEGL 256
#define FSEG 2048
#define NSF 4
#define RL 1024
#define NT 4096
#define NSEG 4

#define OUT_ELEMS (BB*SS_*DD)
#define MASK_OFF  OUT_ELEMS
#define SC_OFF    (OUT_ELEMS + BB*SS_)

// fp32 buffers
__device__ float g_q[NT*DD];
__device__ float g_k[NT*DD];
__device__ float g_v[NT*DD];
__device__ float g_yfin[NT*DD];
__device__ float g_zseg[BB*HH*NSEG*DKV];
__device__ float g_zused[BB*HH*NSEG*DKV];
__device__ float g_dmem[BB*HH*NSEG*DKV*DKV];
__device__ float g_memu[BB*HH*NSEG*DKV*DKV];
__device__ int   g_idx[BB*RL];
__device__ int   g_pos[BB*SS_];
// fp16 activation buffers (hi only)
__device__ __half g_xh[NT*DD];
__device__ __half g_yah[NT*DD];
__device__ __half g_y2h[NT*DD];
__device__ __half g_hh[NT*DHID];
// fp16 weight buffers [K,N]
__device__ __half g_wqh[DD*DD];
__device__ __half g_wkh[DD*DD];
__device__ __half g_wvh[DD*DD];
__device__ __half g_woh[DD*DD];
__device__ __half g_w1h[DD*DHID];
__device__ __half g_w2h[DHID*DD];

__device__ __forceinline__ float sigf(float x){ return x > 0.f ? x + 1.f : __expf(x); }
__device__ __forceinline__ float geluf(float x){ return 0.5f*x*(1.f + erff(x*0.7071067811865476f)); }
__device__ __forceinline__ unsigned pack2h(float x, float y){
    return (unsigned)__half_as_ushort(__float2half_rn(x)) |
           ((unsigned)__half_as_ushort(__float2half_rn(y)) << 16);
}

__global__ void k_cvt_h(const float* __restrict__ s, __half* __restrict__ hi, int n4)
{
    int i = blockIdx.x*256 + threadIdx.x;
    if (i >= n4) return;
    float4 v = ((const float4*)s)[i];
    ((uint2*)hi)[i] = make_uint2(pack2h(v.x, v.y), pack2h(v.z, v.w));
}

// scores + g_pos init fused
__global__ void k_scores(const float* __restrict__ x, const float* __restrict__ ws,
                         const float* __restrict__ bs, float* __restrict__ sc)
{
    int token = blockIdx.x*8 + (threadIdx.x >> 5);
    int lane  = threadIdx.x & 31;
    const float4* xv = (const float4*)(x + (size_t)token*DD);
    const float4* wv = (const float4*)ws;
    double acc = 0.0;
    for (int i = lane; i < 512; i += 32){
        float4 a = xv[i], b = wv[i];
        acc += (double)a.x*b.x + (double)a.y*b.y + (double)a.z*b.z + (double)a.w*b.w;
    }
    #pragma unroll
    for (int o = 16; o; o >>= 1) acc += __shfl_xor_sync(0xFFFFFFFFu, acc, o);
    if (lane == 0){
        sc[token] = (float)acc + bs[0];
        g_pos[token] = -1;
    }
}

__global__ __launch_bounds__(1024) void k_topk(const float* __restrict__ sc)
{
    __shared__ float svv[2048];
    __shared__ int   sii[2048];
    __shared__ int   sel[256];
    int blk = blockIdx.x;
    int b  = blk >> 2;
    int sg = blk & 3;
    int tid = threadIdx.x;
    const float* s = sc + (size_t)b*SS_ + (size_t)sg*FSEG;
    for (int i = tid; i < 2048; i += 1024){ svv[i] = s[i]; sii[i] = i; }
    __syncthreads();
    for (int k2 = 2; k2 <= 2048; k2 <<= 1){
        for (int j = k2 >> 1; j > 0; j >>= 1){
            for (int i = tid; i < 2048; i += 1024){
                int l = i ^ j;
                if (l > i){
                    float vi = svv[i], vl = svv[l];
                    int ii = sii[i], il = sii[l];
                    bool iAfterL = (vi < vl) || (vi == vl && ii > il);
                    bool dir = ((i & k2) == 0);
                    if (dir ? iAfterL : !iAfterL){
                        svv[i] = vl; svv[l] = vi; sii[i] = il; sii[l] = ii;
                    }
                }
            }
            __syncthreads();
        }
    }
    if (tid < 256) sel[tid] = sii[tid];
    __syncthreads();
    for (int k2 = 2; k2 <= 256; k2 <<= 1){
        for (int j = k2 >> 1; j > 0; j >>= 1){
            if (tid < 256){
                int i = tid, l = i ^ j;
                if (l > i){
                    int a = sel[i], c = sel[l];
                    bool dir = ((i & k2) == 0);
                    if (dir ? (a > c) : (a < c)){ sel[i] = c; sel[l] = a; }
                }
            }
            __syncthreads();
        }
    }
    if (tid < 256){
        int gseq = sg*FSEG + sel[tid];
        g_idx[b*RL + sg*SEGL + tid] = gseq;
        g_pos[b*SS_ + gseq] = sg*SEGL + tid;
    }
}

__global__ void k_gather(const float* __restrict__ x)
{
    int r = blockIdx.x;
    int b = r >> 10;
    int src = g_idx[r];
    const float4* sp = (const float4*)(x + ((size_t)b*SS_ + src)*DD);
    uint2* dh = (uint2*)(g_xh + (size_t)r*DD);
    for (int i = threadIdx.x; i < 512; i += 256){
        float4 v = sp[i];
        dh[i] = make_uint2(pack2h(v.x, v.y), pack2h(v.z, v.w));
    }
}

// ---------------- fp16 1-term tensor-core GEMM, KT=64, 3-stage cp.async, 2 CTAs/SM ----------------
__device__ __forceinline__ void ldsm4(unsigned &r0, unsigned &r1, unsigned &r2, unsigned &r3, unsigned addr){
    asm volatile("ldmatrix.sync.aligned.m8n8.x4.shared.b16 {%0,%1,%2,%3},[%4];"
        : "=r"(r0), "=r"(r1), "=r"(r2), "=r"(r3) : "r"(addr));
}
__device__ __forceinline__ void ldsm4t(unsigned &r0, unsigned &r1, unsigned &r2, unsigned &r3, unsigned addr){
    asm volatile("ldmatrix.sync.aligned.m8n8.x4.trans.shared.b16 {%0,%1,%2,%3},[%4];"
        : "=r"(r0), "=r"(r1), "=r"(r2), "=r"(r3) : "r"(addr));
}
__device__ __forceinline__ void mma16816h(float* c, const unsigned* a, unsigned b0, unsigned b1){
    asm volatile("mma.sync.aligned.m16n8k16.row.col.f32.f16.f16.f32 "
        "{%0,%1,%2,%3},{%4,%5,%6,%7},{%8,%9},{%0,%1,%2,%3};"
        : "+f"(c[0]), "+f"(c[1]), "+f"(c[2]), "+f"(c[3])
        : "r"(a[0]), "r"(a[1]), "r"(a[2]), "r"(a[3]), "r"(b0), "r"(b1));
}
__device__ __forceinline__ void cpa16(unsigned s, const void* g){
    asm volatile("cp.async.cg.shared.global [%0],[%1],16;" :: "r"(s), "l"(g));
}

#define LDA 72
#define LDB 136
#define KT 64
#define STG 3
#define O_AH 0
#define O_BH 18432
#define STG_BYTES 35840
#define GEMM_SMEM (STG*STG_BYTES)

// C = A @ B, fp16 single-term. blockIdx.z selects (B_h0,C0) vs (B_h1,C1).
// flags: 1 bias, 2 gelu, 4 write f32 C, 8 write fp16 Chi
__global__ __launch_bounds__(256, 2) void k_gemm_mma(
    const __half* __restrict__ A_h,
    const __half* __restrict__ B_h0, const __half* __restrict__ B_h1,
    const float* __restrict__ bias, float* __restrict__ C0, float* __restrict__ C1,
    __half* __restrict__ Chi,
    int M, int N, int K, int flags)
{
    extern __shared__ __align__(16) char smem[];
    unsigned sbase = (unsigned)__cvta_generic_to_shared(smem);
    const __half* B_h = (blockIdx.z == 0) ? B_h0 : B_h1;
    float* C = (blockIdx.z == 0) ? C0 : C1;
    int tid = threadIdx.x, wid = tid >> 5, lane = tid & 31;
    int rowb = blockIdx.y*128, colb = blockIdx.x*128;
    int wm = wid & 3, wn = wid >> 2;
    float acc[2][8][4];
    #pragma unroll
    for (int i = 0; i < 2; i++)
        #pragma unroll
        for (int j = 0; j < 8; j++)
            #pragma unroll
            for (int u = 0; u < 4; u++) acc[i][j][u] = 0.f;

    unsigned offA0 = ((unsigned)(wm*32 + (lane & 15))*LDA + ((lane >> 4) << 3));
    unsigned offB0 = ((unsigned)(lane & 15))*LDB + (unsigned)(wn*64) + ((lane >> 4) << 3);

    int ktiles = K / KT;

    auto load_stage = [&](int slot, int k0){
        unsigned sb = sbase + (unsigned)slot*STG_BYTES;
        #pragma unroll
        for (int e = 0; e < 4; e++){
            int cc = tid + e*256;
            int row = cc >> 3, kc = (cc & 7)*8;
            size_t go = (size_t)(rowb + row)*K + k0 + kc;
            cpa16(sb + O_AH + (unsigned)(row*LDA + kc)*2, A_h + go);
        }
        #pragma unroll
        for (int e = 0; e < 4; e++){
            int cc = tid + e*256;
            int row = cc >> 4, nc = (cc & 15)*8;
            size_t go = (size_t)(k0 + row)*N + colb + nc;
            cpa16(sb + O_BH + (unsigned)(row*LDB + nc)*2, B_h + go);
        }
    };

    // preload 2 stages
    load_stage(0, 0);
    asm volatile("cp.async.commit_group;" ::: "memory");
    if (ktiles > 1){
        load_stage(1, KT);
        asm volatile("cp.async.commit_group;" ::: "memory");
    }

    for (int t = 0; t < ktiles; t++){
        asm volatile("cp.async.wait_group 1;" ::: "memory");
        __syncthreads();
        int nt_ = t + 2;
        if (nt_ < ktiles){
            load_stage(nt_ % STG, nt_*KT);
            asm volatile("cp.async.commit_group;" ::: "memory");
        }

        unsigned sb = sbase + (unsigned)(t % STG)*STG_BYTES;
        #pragma unroll
        for (int ks = 0; ks < KT; ks += 16){
            unsigned ah[2][4], bh[4][4];
            #pragma unroll
            for (int i = 0; i < 2; i++){
                unsigned off = (offA0 + i*16*LDA + ks)*2;
                ldsm4(ah[i][0], ah[i][1], ah[i][2], ah[i][3], sb + O_AH + off);
            }
            #pragma unroll
            for (int g = 0; g < 4; g++){
                unsigned off = (offB0 + ks*LDB + g*16)*2;
                ldsm4t(bh[g][0], bh[g][1], bh[g][2], bh[g][3], sb + O_BH + off);
            }
            #pragma unroll
            for (int i = 0; i < 2; i++)
                #pragma unroll
                for (int j = 0; j < 8; j++){
                    int g = j >> 1, o = (j & 1)*2;
                    mma16816h(acc[i][j], ah[i], bh[g][o], bh[g][o+1]);
                }
        }
    }

    int g = lane >> 2, t4 = lane & 3;
    #pragma unroll
    for (int i = 0; i < 2; i++){
        int row0 = rowb + wm*32 + i*16 + g;
        #pragma unroll
        for (int j = 0; j < 8; j++){
            int col = colb + wn*64 + j*8 + t4*2;
            float v0 = acc[i][j][0], v1 = acc[i][j][1], v2 = acc[i][j][2], v3 = acc[i][j][3];
            if (flags & 1){
                float b0v = bias[col], b1v = bias[col+1];
                v0 += b0v; v1 += b1v; v2 += b0v; v3 += b1v;
            }
            if (flags & 2){ v0 = geluf(v0); v1 = geluf(v1); v2 = geluf(v2); v3 = geluf(v3); }
            size_t o0 = (size_t)row0*N + col;
            size_t o1 = (size_t)(row0+8)*N + col;
            if (flags & 4){
                *(float2*)&C[o0] = make_float2(v0, v1);
                *(float2*)&C[o1] = make_float2(v2, v3);
            }
            if (flags & 8){
                *(unsigned*)&Chi[o0] = pack2h(v0, v1);
                *(unsigned*)&Chi[o1] = pack2h(v2, v3);
            }
        }
    }
}

// dmem = sig(k)^T @ v, with fused z-segment column sums
__global__ __launch_bounds__(256) void k_dmem()
{
    __shared__ float sk[16][132];
    __shared__ float sv[16][128];
    int bhs = blockIdx.x;
    int bh = bhs >> 2, s = bhs & 3;
    int b = bh >> 4, h = bh & 15;
    int tid = threadIdx.x;
    int td = tid >> 4, tv = tid & 15;
    float acc[8][8];
    #pragma unroll
    for (int i = 0; i < 8; i++)
        #pragma unroll
        for (int j = 0; j < 8; j++) acc[i][j] = 0.f;
    float zacc = 0.f;
    int zd = tid & 127;
    size_t base = (size_t)(b*RL + s*SEGL)*DD + h*DKV;
    for (int j0 = 0; j0 < SEGL; j0 += 16){
        for (int e = tid; e < 512; e += 256){
            int r = e >> 5, c = e & 31;
            float4 kv = *(const float4*)&g_k[base + (size_t)(j0 + r)*DD + c*4];
            sk[r][c*4+0] = sigf(kv.x); sk[r][c*4+1] = sigf(kv.y);
            sk[r][c*4+2] = sigf(kv.z); sk[r][c*4+3] = sigf(kv.w);
            *(float4*)&sv[r][c*4] = *(const float4*)&g_v[base + (size_t)(j0 + r)*DD + c*4];
        }
        __syncthreads();
        if (tid < 128){
            #pragma unroll
            for (int jj = 0; jj < 16; jj++) zacc += sk[jj][zd];
        }
        #pragma unroll
        for (int jj = 0; jj < 16; jj++){
            float a[8], bv[8];
            #pragma unroll
            for (int u = 0; u < 8; u++) a[u] = sk[jj][td*8+u];
            *(float4*)&bv[0] = *(float4*)&sv[jj][tv*8];
            *(float4*)&bv[4] = *(float4*)&sv[jj][tv*8+4];
            #pragma unroll
            for (int i = 0; i < 8; i++)
                #pragma unroll
                for (int j = 0; j < 8; j++) acc[i][j] += a[i]*bv[j];
        }
        __syncthreads();
    }
    if (tid < 128) g_zseg[(size_t)bhs*DKV + zd] = zacc;
    float* outp = g_dmem + (size_t)bhs*DKV*DKV;
    #pragma unroll
    for (int i = 0; i < 8; i++){
        *(float4*)&outp[(td*8+i)*DKV + tv*8]     = *(float4*)&acc[i][0];
        *(float4*)&outp[(td*8+i)*DKV + tv*8 + 4] = *(float4*)&acc[i][4];
    }
}

// fused z prefix (tid<128) + mem prefix
__global__ __launch_bounds__(256) void k_zmpref()
{
    int bh = blockIdx.x;
    int tid = threadIdx.x;
    if (tid < 128){
        float z = 1.f/128.f;
        #pragma unroll
        for (int s = 0; s < NSEG; s++){
            g_zused[(bh*NSEG + s)*DKV + tid] = z;
            z += g_zseg[(bh*NSEG + s)*DKV + tid];
        }
    }
    for (int e = tid; e < DKV*DKV; e += 256){
        float a = 0.f;
        #pragma unroll
        for (int s = 0; s < NSEG; s++){
            size_t off = ((size_t)(bh*NSEG + s))*DKV*DKV + e;
            g_memu[off] = a;
            a += g_dmem[off];
        }
    }
}

__global__ __launch_bounds__(256) void k_attn(const float* __restrict__ betas)
{
    __shared__ float pool[8192];
    int bhs = blockIdx.x;
    int bh = bhs >> 2, s = bhs & 3;
    int b = bh >> 4, h = bh & 15;
    int rc = blockIdx.y;
    int tid = threadIdx.x;
    int rloc = tid >> 2, vq = tid & 3;
    int i = rc*64 + rloc;
    int tok = b*RL + s*SEGL + i;
    const float* qrow = g_q + (size_t)tok*DD + h*DKV;

    float m = -INFINITY, l = 0.f;
    float4 accd[8];
    #pragma unroll
    for (int u = 0; u < 8; u++) accd[u] = make_float4(0.f,0.f,0.f,0.f);
    {
        float4 qf[8];
        const float4* qp = (const float4*)(qrow + vq*32);
        #pragma unroll
        for (int u = 0; u < 8; u++) qf[u] = qp[u];
        int ntiles = rc*2 + 2;
        size_t kvbase = (size_t)(b*RL + s*SEGL)*DD + h*DKV;
        for (int t0 = 0; t0 < ntiles; t0++){
            __syncthreads();
            for (int e = tid; e < 1024; e += 256){
                int r = e >> 5, c = e & 31;
                size_t src = kvbase + (size_t)(t0*32 + r)*DD + c*4;
                *(float4*)&pool[r*128 + c*4]        = *(const float4*)&g_k[src];
                *(float4*)&pool[4096 + r*128 + c*4] = *(const float4*)&g_v[src];
            }
            __syncthreads();
            for (int jj = 0; jj < 32; jj++){
                int j = t0*32 + jj;
                float sp = 0.f;
                const float4* kr = (const float4*)&pool[jj*128 + vq*32];
                #pragma unroll
                for (int u = 0; u < 8; u++){
                    float4 kv = kr[u];
                    sp += qf[u].x*kv.x + qf[u].y*kv.y + qf[u].z*kv.z + qf[u].w*kv.w;
                }
                sp += __shfl_xor_sync(0xFFFFFFFFu, sp, 1);
                sp += __shfl_xor_sync(0xFFFFFFFFu, sp, 2);
                if (j <= i){
                    sp *= 0.08838834764831845f;
                    float mn = fmaxf(m, sp);
                    float cor = __expf(m - mn);
                    float p = __expf(sp - mn);
                    l = l*cor + p;
                    const float4* vr = (const float4*)&pool[4096 + jj*128 + vq*32];
                    #pragma unroll
                    for (int u = 0; u < 8; u++){
                        float4 vv = vr[u];
                        accd[u].x = accd[u].x*cor + p*vv.x;
                        accd[u].y = accd[u].y*cor + p*vv.y;
                        accd[u].z = accd[u].z*cor + p*vv.z;
                        accd[u].w = accd[u].w*cor + p*vv.w;
                    }
                    m = mn;
                }
            }
        }
    }
    float linv = 1.f / l;

    float4 accm[8];
    #pragma unroll
    for (int u = 0; u < 8; u++) accm[u] = make_float4(0.f,0.f,0.f,0.f);
    float denom = 0.f;
    const float* zu = g_zused + (bh*NSEG + s)*DKV;
    const float* mbase = g_memu + (size_t)(bh*NSEG + s)*DKV*DKV;
    for (int c0 = 0; c0 < 2; c0++){
        __syncthreads();
        for (int e = tid; e < 2048; e += 256){
            int r = e >> 5, cc = e & 31;
            *(float4*)&pool[r*128 + cc*4] = *(const float4*)&mbase[(size_t)(c0*64 + r)*DKV + cc*4];
        }
        __syncthreads();
        for (int dd = 0; dd < 64; dd++){
            int d = c0*64 + dd;
            float coef = sigf(qrow[d]);
            denom += coef * zu[d];
            const float4* mr = (const float4*)&pool[dd*128 + vq*32];
            #pragma unroll
            for (int u = 0; u < 8; u++){
                float4 mv = mr[u];
                accm[u].x += coef*mv.x; accm[u].y += coef*mv.y;
                accm[u].z += coef*mv.z; accm[u].w += coef*mv.w;
            }
        }
    }
    float dinv = 1.f / denom;

    unsigned* yh = (unsigned*)(g_yah + (size_t)tok*DD + h*DKV + vq*32);
    const float* bet = betas + h*DKV + vq*32;
    #pragma unroll
    for (int u = 0; u < 8; u++){
        float4 o;
        float g0 = 1.f/(1.f + __expf(-bet[u*4+0]));
        float g1 = 1.f/(1.f + __expf(-bet[u*4+1]));
        float g2 = 1.f/(1.f + __expf(-bet[u*4+2]));
        float g3 = 1.f/(1.f + __expf(-bet[u*4+3]));
        o.x = g0*(accm[u].x*dinv) + (1.f - g0)*(accd[u].x*linv);
        o.y = g1*(accm[u].y*dinv) + (1.f - g1)*(accd[u].y*linv);
        o.z = g2*(accm[u].z*dinv) + (1.f - g2)*(accd[u].z*linv);
        o.w = g3*(accm[u].w*dinv) + (1.f - g3)*(accd[u].w*linv);
        yh[u*2]   = pack2h(o.x, o.y);
        yh[u*2+1] = pack2h(o.z, o.w);
    }
}

__global__ __launch_bounds__(256) void k_ln(const float* __restrict__ x,
                                            const float* __restrict__ lw, const float* __restrict__ lb,
                                            float* __restrict__ out, float* __restrict__ maskout)
{
    __shared__ float red[8];
    int token = blockIdx.x;
    int tid = threadIdx.x;
    int b = token >> 13;
    int p = g_pos[token];
    const float4* xp = (const float4*)(x + (size_t)token*DD);
    float4 v0 = xp[tid], v1 = xp[tid + 256];
    if (p >= 0){
        const float4* yp = (const float4*)(g_yfin + (size_t)(b*RL + p)*DD);
        float4 a = yp[tid], c = yp[tid + 256];
        v0.x += a.x; v0.y += a.y; v0.z += a.z; v0.w += a.w;
        v1.x += c.x; v1.y += c.y; v1.z += c.z; v1.w += c.w;
    }
    float sm = v0.x+v0.y+v0.z+v0.w + v1.x+v1.y+v1.z+v1.w;
    #pragma unroll
    for (int o = 16; o; o >>= 1) sm += __shfl_xor_sync(0xFFFFFFFFu, sm, o);
    int w = tid >> 5, lane = tid & 31;
    if (lane == 0) red[w] = sm;
    __syncthreads();
    float tot = 0.f;
    #pragma unroll
    for (int u = 0; u < 8; u++) tot += red[u];
    float mu = tot * (1.f/2048.f);
    __syncthreads();
    float d0 = v0.x-mu, d1 = v0.y-mu, d2 = v0.z-mu, d3 = v0.w-mu;
    float d4 = v1.x-mu, d5 = v1.y-mu, d6 = v1.z-mu, d7 = v1.w-mu;
    float sq = d0*d0+d1*d1+d2*d2+d3*d3+d4*d4+d5*d5+d6*d6+d7*d7;
    #pragma unroll
    for (int o = 16; o; o >>= 1) sq += __shfl_xor_sync(0xFFFFFFFFu, sq, o);
    if (lane == 0) red[w] = sq;
    __syncthreads();
    float tot2 = 0.f;
    #pragma unroll
    for (int u = 0; u < 8; u++) tot2 += red[u];
    float rstd = rsqrtf(tot2 * (1.f/2048.f) + 1e-5f);
    float4 w0 = ((const float4*)lw)[tid], w1_ = ((const float4*)lw)[tid + 256];
    float4 bb0 = ((const float4*)lb)[tid], bb1 = ((const float4*)lb)[tid + 256];
    float4 o0, o1;
    o0.x = d0*rstd*w0.x + bb0.x;  o0.y = d1*rstd*w0.y + bb0.y;
    o0.z = d2*rstd*w0.z + bb0.z;  o0.w = d3*rstd*w0.w + bb0.w;
    o1.x = d4*rstd*w1_.x + bb1.x; o1.y = d5*rstd*w1_.y + bb1.y;
    o1.z = d6*rstd*w1_.z + bb1.z; o1.w = d7*rstd*w1_.w + bb1.w;
    ((float4*)(out + (size_t)token*DD))[tid]       = o0;
    ((float4*)(out + (size_t)token*DD))[tid + 256] = o1;
    if (tid == 0) maskout[token] = (p >= 0) ? 1.f : 0.f;
}

extern "C" void kernel_launch(void* const* d_in, const int* in_sizes, int n_in,
                              void* d_out, int out_size)
{
    const float* x     = (const float*)d_in[0];
    const float* wq    = (const float*)d_in[1];
    const float* wk    = (const float*)d_in[2];
    const float* wv    = (const float*)d_in[3];
    const float* betas = (const float*)d_in[4];
    const float* wo    = (const float*)d_in[5];
    const float* w1    = (const float*)d_in[6];
    const float* b1    = (const float*)d_in[7];
    const float* w2    = (const float*)d_in[8];
    const float* b2    = (const float*)d_in[9];
    const float* lnw   = (const float*)d_in[10];
    const float* lnb   = (const float*)d_in[11];
    const float* wsamp = (const float*)d_in[12];
    const float* bsamp = (const float*)d_in[13];
    float* out = (float*)d_out;
    float* maskout = out + MASK_OFF;
    float* scout   = out + SC_OFF;

    static int cfg = 0;
    if (!cfg){
        cudaFuncSetAttribute(k_gemm_mma, cudaFuncAttributeMaxDynamicSharedMemorySize, GEMM_SMEM);
        cfg = 1;
    }

    #define SYM(T, p, s) T p; cudaGetSymbolAddress((void**)&p, s)
    SYM(float*, pq, g_q); SYM(float*, pk, g_k); SYM(float*, pv, g_v); SYM(float*, pyf, g_yfin);
    SYM(__half*, pxh, g_xh);
    SYM(__half*, pyah, g_yah);
    SYM(__half*, py2h, g_y2h);
    SYM(__half*, phh, g_hh);
    SYM(__half*, pwqh, g_wqh);
    SYM(__half*, pwkh, g_wkh);
    SYM(__half*, pwvh, g_wvh);
    SYM(__half*, pwoh, g_woh);
    SYM(__half*, pw1h, g_w1h);
    SYM(__half*, pw2h, g_w2h);
    #undef SYM

    k_scores<<<BB*SS_/8, 256>>>(x, wsamp, bsamp, scout);
    k_topk<<<BB*NSF, 1024>>>(scout);
    k_gather<<<NT, 256>>>(x);
    k_cvt_h<<<(DD*DD/4+255)/256, 256>>>(wq, pwqh, DD*DD/4);

    dim3 g1(DD/128, NT/128, 1);
    k_gemm_mma<<<g1, 256, GEMM_SMEM>>>(pxh, pwqh, nullptr, nullptr,
                                       pq, nullptr, nullptr, NT, DD, DD, 4);

    k_cvt_h<<<(DD*DD/4+255)/256, 256>>>(wk, pwkh, DD*DD/4);
    k_cvt_h<<<(DD*DD/4+255)/256, 256>>>(wv, pwvh, DD*DD/4);
    dim3 gkv(DD/128, NT/128, 2);
    k_gemm_mma<<<gkv, 256, GEMM_SMEM>>>(pxh, pwkh, pwvh, nullptr,
                                        pk, pv, nullptr, NT, DD, DD, 4);

    k_cvt_h<<<(DD*DD/4+255)/256, 256>>>(wo, pwoh, DD*DD/4);
    k_cvt_h<<<(DD*DHID/4+255)/256, 256>>>(w1, pw1h, DD*DHID/4);
    k_cvt_h<<<(DHID*DD/4+255)/256, 256>>>(w2, pw2h, DHID*DD/4);

    k_dmem<<<BB*HH*NSEG, 256>>>();
    k_zmpref<<<BB*HH, 256>>>();

    dim3 ga(BB*HH*NSEG, 4);
    k_attn<<<ga, 256>>>(betas);

    k_gemm_mma<<<g1, 256, GEMM_SMEM>>>(pyah, pwoh, nullptr, nullptr,
                                       nullptr, nullptr, py2h, NT, DD, DD, 8);
    dim3 g2(DHID/128, NT/128, 1);
    k_gemm_mma<<<g2, 256, GEMM_SMEM>>>(py2h, pw1h, nullptr, b1,
                                       nullptr, nullptr, phh, NT, DHID, DD, 11);
    k_gemm_mma<<<g1, 256, GEMM_SMEM>>>(phh, pw2h, nullptr, b2,
                                       pyf, nullptr, nullptr, NT, DD, DHID, 5);

    k_ln<<<BB*SS_, 256>>>(x, lnw, lnb, out, maskout);
}

// round 17
// speedup vs baseline: 1.0072x; 1.0072x over previous
#include <cuda_runtime.h>
#include <cuda_fp16.h>
#include <math.h>

#define BB 4
#define SS_ 8192
#define DD 2048
#define HH 16
#define DKV 128
#define DHID 8192
#define SEGL 256
#define FSEG 2048
#define NSF 4
#define RL 1024
#define NT 4096
#define NSEG 4

#define OUT_ELEMS (BB*SS_*DD)
#define MASK_OFF  OUT_ELEMS
#define SC_OFF    (OUT_ELEMS + BB*SS_)

// fp32 buffers
__device__ float g_yfin[NT*DD];
__device__ float g_zseg[BB*HH*NSEG*DKV];
__device__ float g_zused[BB*HH*NSEG*DKV];
__device__ float g_dmem[BB*HH*NSEG*DKV*DKV];
__device__ float g_memu[BB*HH*NSEG*DKV*DKV];
__device__ int   g_idx[BB*RL];
__device__ int   g_pos[BB*SS_];
// fp16 activation buffers
__device__ __half g_xh[NT*DD];
__device__ __half g_qh[NT*DD];
__device__ __half g_kh[NT*DD];
__device__ __half g_vh[NT*DD];
__device__ __half g_yah[NT*DD];
__device__ __half g_y2h[NT*DD];
__device__ __half g_hh[NT*DHID];
// fp16 weight buffers [K,N]
__device__ __half g_wqh[DD*DD];
__device__ __half g_wkh[DD*DD];
__device__ __half g_wvh[DD*DD];
__device__ __half g_woh[DD*DD];
__device__ __half g_w1h[DD*DHID];
__device__ __half g_w2h[DHID*DD];

__device__ __forceinline__ float sigf(float x){ return x > 0.f ? x + 1.f : __expf(x); }
__device__ __forceinline__ float geluf(float x){ return 0.5f*x*(1.f + erff(x*0.7071067811865476f)); }
__device__ __forceinline__ unsigned pack2h(float x, float y){
    return (unsigned)__half_as_ushort(__float2half_rn(x)) |
           ((unsigned)__half_as_ushort(__float2half_rn(y)) << 16);
}
// unpack 8 halves (uint4) -> 8 floats
__device__ __forceinline__ void h8f(uint4 h, float* f){
    __half2* hp = (__half2*)&h;
    #pragma unroll
    for (int w = 0; w < 4; w++){
        float2 t = __half22float2(hp[w]);
        f[w*2] = t.x; f[w*2+1] = t.y;
    }
}

__global__ void k_cvt_h(const float* __restrict__ s, __half* __restrict__ hi, int n4)
{
    int i = blockIdx.x*256 + threadIdx.x;
    if (i >= n4) return;
    float4 v = ((const float4*)s)[i];
    ((uint2*)hi)[i] = make_uint2(pack2h(v.x, v.y), pack2h(v.z, v.w));
}

// scores + g_pos init fused
__global__ void k_scores(const float* __restrict__ x, const float* __restrict__ ws,
                         const float* __restrict__ bs, float* __restrict__ sc)
{
    int token = blockIdx.x*8 + (threadIdx.x >> 5);
    int lane  = threadIdx.x & 31;
    const float4* xv = (const float4*)(x + (size_t)token*DD);
    const float4* wv = (const float4*)ws;
    double acc = 0.0;
    for (int i = lane; i < 512; i += 32){
        float4 a = xv[i], b = wv[i];
        acc += (double)a.x*b.x + (double)a.y*b.y + (double)a.z*b.z + (double)a.w*b.w;
    }
    #pragma unroll
    for (int o = 16; o; o >>= 1) acc += __shfl_xor_sync(0xFFFFFFFFu, acc, o);
    if (lane == 0){
        sc[token] = (float)acc + bs[0];
        g_pos[token] = -1;
    }
}

__global__ __launch_bounds__(1024) void k_topk(const float* __restrict__ sc)
{
    __shared__ float svv[2048];
    __shared__ int   sii[2048];
    __shared__ int   sel[256];
    int blk = blockIdx.x;
    int b  = blk >> 2;
    int sg = blk & 3;
    int tid = threadIdx.x;
    const float* s = sc + (size_t)b*SS_ + (size_t)sg*FSEG;
    for (int i = tid; i < 2048; i += 1024){ svv[i] = s[i]; sii[i] = i; }
    __syncthreads();
    for (int k2 = 2; k2 <= 2048; k2 <<= 1){
        for (int j = k2 >> 1; j > 0; j >>= 1){
            for (int i = tid; i < 2048; i += 1024){
                int l = i ^ j;
                if (l > i){
                    float vi = svv[i], vl = svv[l];
                    int ii = sii[i], il = sii[l];
                    bool iAfterL = (vi < vl) || (vi == vl && ii > il);
                    bool dir = ((i & k2) == 0);
                    if (dir ? iAfterL : !iAfterL){
                        svv[i] = vl; svv[l] = vi; sii[i] = il; sii[l] = ii;
                    }
                }
            }
            __syncthreads();
        }
    }
    if (tid < 256) sel[tid] = sii[tid];
    __syncthreads();
    for (int k2 = 2; k2 <= 256; k2 <<= 1){
        for (int j = k2 >> 1; j > 0; j >>= 1){
            if (tid < 256){
                int i = tid, l = i ^ j;
                if (l > i){
                    int a = sel[i], c = sel[l];
                    bool dir = ((i & k2) == 0);
                    if (dir ? (a > c) : (a < c)){ sel[i] = c; sel[l] = a; }
                }
            }
            __syncthreads();
        }
    }
    if (tid < 256){
        int gseq = sg*FSEG + sel[tid];
        g_idx[b*RL + sg*SEGL + tid] = gseq;
        g_pos[b*SS_ + gseq] = sg*SEGL + tid;
    }
}

__global__ void k_gather(const float* __restrict__ x)
{
    int r = blockIdx.x;
    int b = r >> 10;
    int src = g_idx[r];
    const float4* sp = (const float4*)(x + ((size_t)b*SS_ + src)*DD);
    uint2* dh = (uint2*)(g_xh + (size_t)r*DD);
    for (int i = threadIdx.x; i < 512; i += 256){
        float4 v = sp[i];
        dh[i] = make_uint2(pack2h(v.x, v.y), pack2h(v.z, v.w));
    }
}

// ---------------- fp16 1-term tensor-core GEMM, KT=64, 3-stage cp.async, 2 CTAs/SM ----------------
__device__ __forceinline__ void ldsm4(unsigned &r0, unsigned &r1, unsigned &r2, unsigned &r3, unsigned addr){
    asm volatile("ldmatrix.sync.aligned.m8n8.x4.shared.b16 {%0,%1,%2,%3},[%4];"
        : "=r"(r0), "=r"(r1), "=r"(r2), "=r"(r3) : "r"(addr));
}
__device__ __forceinline__ void ldsm4t(unsigned &r0, unsigned &r1, unsigned &r2, unsigned &r3, unsigned addr){
    asm volatile("ldmatrix.sync.aligned.m8n8.x4.trans.shared.b16 {%0,%1,%2,%3},[%4];"
        : "=r"(r0), "=r"(r1), "=r"(r2), "=r"(r3) : "r"(addr));
}
__device__ __forceinline__ void mma16816h(float* c, const unsigned* a, unsigned b0, unsigned b1){
    asm volatile("mma.sync.aligned.m16n8k16.row.col.f32.f16.f16.f32 "
        "{%0,%1,%2,%3},{%4,%5,%6,%7},{%8,%9},{%0,%1,%2,%3};"
        : "+f"(c[0]), "+f"(c[1]), "+f"(c[2]), "+f"(c[3])
        : "r"(a[0]), "r"(a[1]), "r"(a[2]), "r"(a[3]), "r"(b0), "r"(b1));
}
__device__ __forceinline__ void cpa16(unsigned s, const void* g){
    asm volatile("cp.async.cg.shared.global [%0],[%1],16;" :: "r"(s), "l"(g));
}

#define LDA 72
#define LDB 136
#define KT 64
#define STG 3
#define O_AH 0
#define O_BH 18432
#define STG_BYTES 35840
#define GEMM_SMEM (STG*STG_BYTES)

// C = A @ B, fp16 single-term. blockIdx.z selects (B_h0,Chi0) vs (B_h1,Chi1).
// flags: 1 bias, 2 gelu, 4 write f32 C0, 8 write fp16 Chi
__global__ __launch_bounds__(256, 2) void k_gemm_mma(
    const __half* __restrict__ A_h,
    const __half* __restrict__ B_h0, const __half* __restrict__ B_h1,
    const float* __restrict__ bias, float* __restrict__ C0,
    __half* __restrict__ Chi0, __half* __restrict__ Chi1,
    int M, int N, int K, int flags)
{
    extern __shared__ __align__(16) char smem[];
    unsigned sbase = (unsigned)__cvta_generic_to_shared(smem);
    const __half* B_h = (blockIdx.z == 0) ? B_h0 : B_h1;
    __half* Chi = (blockIdx.z == 0) ? Chi0 : Chi1;
    int tid = threadIdx.x, wid = tid >> 5, lane = tid & 31;
    int rowb = blockIdx.y*128, colb = blockIdx.x*128;
    int wm = wid & 3, wn = wid >> 2;
    float acc[2][8][4];
    #pragma unroll
    for (int i = 0; i < 2; i++)
        #pragma unroll
        for (int j = 0; j < 8; j++)
            #pragma unroll
            for (int u = 0; u < 4; u++) acc[i][j][u] = 0.f;

    unsigned offA0 = ((unsigned)(wm*32 + (lane & 15))*LDA + ((lane >> 4) << 3));
    unsigned offB0 = ((unsigned)(lane & 15))*LDB + (unsigned)(wn*64) + ((lane >> 4) << 3);

    int ktiles = K / KT;

    auto load_stage = [&](int slot, int k0){
        unsigned sb = sbase + (unsigned)slot*STG_BYTES;
        #pragma unroll
        for (int e = 0; e < 4; e++){
            int cc = tid + e*256;
            int row = cc >> 3, kc = (cc & 7)*8;
            size_t go = (size_t)(rowb + row)*K + k0 + kc;
            cpa16(sb + O_AH + (unsigned)(row*LDA + kc)*2, A_h + go);
        }
        #pragma unroll
        for (int e = 0; e < 4; e++){
            int cc = tid + e*256;
            int row = cc >> 4, nc = (cc & 15)*8;
            size_t go = (size_t)(k0 + row)*N + colb + nc;
            cpa16(sb + O_BH + (unsigned)(row*LDB + nc)*2, B_h + go);
        }
    };

    load_stage(0, 0);
    asm volatile("cp.async.commit_group;" ::: "memory");
    if (ktiles > 1){
        load_stage(1, KT);
        asm volatile("cp.async.commit_group;" ::: "memory");
    }

    for (int t = 0; t < ktiles; t++){
        asm volatile("cp.async.wait_group 1;" ::: "memory");
        __syncthreads();
        int nt_ = t + 2;
        if (nt_ < ktiles){
            load_stage(nt_ % STG, nt_*KT);
            asm volatile("cp.async.commit_group;" ::: "memory");
        }

        unsigned sb = sbase + (unsigned)(t % STG)*STG_BYTES;
        #pragma unroll
        for (int ks = 0; ks < KT; ks += 16){
            unsigned ah[2][4], bh[4][4];
            #pragma unroll
            for (int i = 0; i < 2; i++){
                unsigned off = (offA0 + i*16*LDA + ks)*2;
                ldsm4(ah[i][0], ah[i][1], ah[i][2], ah[i][3], sb + O_AH + off);
            }
            #pragma unroll
            for (int g = 0; g < 4; g++){
                unsigned off = (offB0 + ks*LDB + g*16)*2;
                ldsm4t(bh[g][0], bh[g][1], bh[g][2], bh[g][3], sb + O_BH + off);
            }
            #pragma unroll
            for (int i = 0; i < 2; i++)
                #pragma unroll
                for (int j = 0; j < 8; j++){
                    int g = j >> 1, o = (j & 1)*2;
                    mma16816h(acc[i][j], ah[i], bh[g][o], bh[g][o+1]);
                }
        }
    }

    int g = lane >> 2, t4 = lane & 3;
    #pragma unroll
    for (int i = 0; i < 2; i++){
        int row0 = rowb + wm*32 + i*16 + g;
        #pragma unroll
        for (int j = 0; j < 8; j++){
            int col = colb + wn*64 + j*8 + t4*2;
            float v0 = acc[i][j][0], v1 = acc[i][j][1], v2 = acc[i][j][2], v3 = acc[i][j][3];
            if (flags & 1){
                float b0v = bias[col], b1v = bias[col+1];
                v0 += b0v; v1 += b1v; v2 += b0v; v3 += b1v;
            }
            if (flags & 2){ v0 = geluf(v0); v1 = geluf(v1); v2 = geluf(v2); v3 = geluf(v3); }
            size_t o0 = (size_t)row0*N + col;
            size_t o1 = (size_t)(row0+8)*N + col;
            if (flags & 4){
                *(float2*)&C0[o0] = make_float2(v0, v1);
                *(float2*)&C0[o1] = make_float2(v2, v3);
            }
            if (flags & 8){
                *(unsigned*)&Chi[o0] = pack2h(v0, v1);
                *(unsigned*)&Chi[o1] = pack2h(v2, v3);
            }
        }
    }
}

// dmem = sig(k)^T @ v (fp16 inputs, fp32 math), with fused z-segment column sums
__global__ __launch_bounds__(256) void k_dmem()
{
    __shared__ float sk[16][132];
    __shared__ float sv[16][128];
    int bhs = blockIdx.x;
    int bh = bhs >> 2, s = bhs & 3;
    int b = bh >> 4, h = bh & 15;
    int tid = threadIdx.x;
    int td = tid >> 4, tv = tid & 15;
    float acc[8][8];
    #pragma unroll
    for (int i = 0; i < 8; i++)
        #pragma unroll
        for (int j = 0; j < 8; j++) acc[i][j] = 0.f;
    float zacc = 0.f;
    int zd = tid & 127;
    size_t base = (size_t)(b*RL + s*SEGL)*DD + h*DKV;
    for (int j0 = 0; j0 < SEGL; j0 += 16){
        {
            int r = tid >> 4, c = (tid & 15)*8;
            float kf[8], vf[8];
            h8f(*(const uint4*)&g_kh[base + (size_t)(j0 + r)*DD + c], kf);
            h8f(*(const uint4*)&g_vh[base + (size_t)(j0 + r)*DD + c], vf);
            #pragma unroll
            for (int u = 0; u < 8; u++) sk[r][c+u] = sigf(kf[u]);
            *(float4*)&sv[r][c]   = make_float4(vf[0], vf[1], vf[2], vf[3]);
            *(float4*)&sv[r][c+4] = make_float4(vf[4], vf[5], vf[6], vf[7]);
        }
        __syncthreads();
        if (tid < 128){
            #pragma unroll
            for (int jj = 0; jj < 16; jj++) zacc += sk[jj][zd];
        }
        #pragma unroll
        for (int jj = 0; jj < 16; jj++){
            float a[8], bv[8];
            #pragma unroll
            for (int u = 0; u < 8; u++) a[u] = sk[jj][td*8+u];
            *(float4*)&bv[0] = *(float4*)&sv[jj][tv*8];
            *(float4*)&bv[4] = *(float4*)&sv[jj][tv*8+4];
            #pragma unroll
            for (int i = 0; i < 8; i++)
                #pragma unroll
                for (int j = 0; j < 8; j++) acc[i][j] += a[i]*bv[j];
        }
        __syncthreads();
    }
    if (tid < 128) g_zseg[(size_t)bhs*DKV + zd] = zacc;
    float* outp = g_dmem + (size_t)bhs*DKV*DKV;
    #pragma unroll
    for (int i = 0; i < 8; i++){
        *(float4*)&outp[(td*8+i)*DKV + tv*8]     = *(float4*)&acc[i][0];
        *(float4*)&outp[(td*8+i)*DKV + tv*8 + 4] = *(float4*)&acc[i][4];
    }
}

// fused z prefix (tid<128) + mem prefix
__global__ __launch_bounds__(256) void k_zmpref()
{
    int bh = blockIdx.x;
    int tid = threadIdx.x;
    if (tid < 128){
        float z = 1.f/128.f;
        #pragma unroll
        for (int s = 0; s < NSEG; s++){
            g_zused[(bh*NSEG + s)*DKV + tid] = z;
            z += g_zseg[(bh*NSEG + s)*DKV + tid];
        }
    }
    for (int e = tid; e < DKV*DKV; e += 256){
        float a = 0.f;
        #pragma unroll
        for (int s = 0; s < NSEG; s++){
            size_t off = ((size_t)(bh*NSEG + s))*DKV*DKV + e;
            g_memu[off] = a;
            a += g_dmem[off];
        }
    }
}

__global__ __launch_bounds__(256) void k_attn(const float* __restrict__ betas)
{
    __shared__ float pool[8192];
    int bhs = blockIdx.x;
    int bh = bhs >> 2, s = bhs & 3;
    int b = bh >> 4, h = bh & 15;
    int rc = blockIdx.y;
    int tid = threadIdx.x;
    int rloc = tid >> 2, vq = tid & 3;
    int i = rc*64 + rloc;
    int tok = b*RL + s*SEGL + i;
    const __half* qrow = g_qh + (size_t)tok*DD + h*DKV;

    float m = -INFINITY, l = 0.f;
    float4 accd[8];
    #pragma unroll
    for (int u = 0; u < 8; u++) accd[u] = make_float4(0.f,0.f,0.f,0.f);
    {
        float qv[32];
        {
            const uint4* qp = (const uint4*)(qrow + vq*32);
            #pragma unroll
            for (int u = 0; u < 4; u++) h8f(qp[u], qv + u*8);
        }
        int ntiles = rc*2 + 2;
        size_t kvbase = (size_t)(b*RL + s*SEGL)*DD + h*DKV;
        for (int t0 = 0; t0 < ntiles; t0++){
            __syncthreads();
            for (int e = tid; e < 512; e += 256){
                int r = e >> 4, c = (e & 15)*8;
                size_t src = kvbase + (size_t)(t0*32 + r)*DD + c;
                float kf[8], vf[8];
                h8f(*(const uint4*)&g_kh[src], kf);
                h8f(*(const uint4*)&g_vh[src], vf);
                *(float4*)&pool[r*128 + c]          = make_float4(kf[0], kf[1], kf[2], kf[3]);
                *(float4*)&pool[r*128 + c + 4]      = make_float4(kf[4], kf[5], kf[6], kf[7]);
                *(float4*)&pool[4096 + r*128 + c]   = make_float4(vf[0], vf[1], vf[2], vf[3]);
                *(float4*)&pool[4096 + r*128 + c+4] = make_float4(vf[4], vf[5], vf[6], vf[7]);
            }
            __syncthreads();
            for (int jj = 0; jj < 32; jj++){
                int j = t0*32 + jj;
                float sp = 0.f;
                const float4* kr = (const float4*)&pool[jj*128 + vq*32];
                #pragma unroll
                for (int u = 0; u < 8; u++){
                    float4 kv = kr[u];
                    sp += qv[u*4+0]*kv.x + qv[u*4+1]*kv.y + qv[u*4+2]*kv.z + qv[u*4+3]*kv.w;
                }
                sp += __shfl_xor_sync(0xFFFFFFFFu, sp, 1);
                sp += __shfl_xor_sync(0xFFFFFFFFu, sp, 2);
                if (j <= i){
                    sp *= 0.08838834764831845f;
                    float mn = fmaxf(m, sp);
                    float cor = __expf(m - mn);
                    float p = __expf(sp - mn);
                    l = l*cor + p;
                    const float4* vr = (const float4*)&pool[4096 + jj*128 + vq*32];
                    #pragma unroll
                    for (int u = 0; u < 8; u++){
                        float4 vv = vr[u];
                        accd[u].x = accd[u].x*cor + p*vv.x;
                        accd[u].y = accd[u].y*cor + p*vv.y;
                        accd[u].z = accd[u].z*cor + p*vv.z;
                        accd[u].w = accd[u].w*cor + p*vv.w;
                    }
                    m = mn;
                }
            }
        }
    }
    float linv = 1.f / l;

    float4 accm[8];
    #pragma unroll
    for (int u = 0; u < 8; u++) accm[u] = make_float4(0.f,0.f,0.f,0.f);
    float denom = 0.f;
    const float* zu = g_zused + (bh*NSEG + s)*DKV;
    const float* mbase = g_memu + (size_t)(bh*NSEG + s)*DKV*DKV;
    for (int c0 = 0; c0 < 2; c0++){
        __syncthreads();
        for (int e = tid; e < 2048; e += 256){
            int r = e >> 5, cc = e & 31;
            *(float4*)&pool[r*128 + cc*4] = *(const float4*)&mbase[(size_t)(c0*64 + r)*DKV + cc*4];
        }
        __syncthreads();
        for (int dd = 0; dd < 64; dd++){
            int d = c0*64 + dd;
            float coef = sigf(__half2float(qrow[d]));
            denom += coef * zu[d];
            const float4* mr = (const float4*)&pool[dd*128 + vq*32];
            #pragma unroll
            for (int u = 0; u < 8; u++){
                float4 mv = mr[u];
                accm[u].x += coef*mv.x; accm[u].y += coef*mv.y;
                accm[u].z += coef*mv.z; accm[u].w += coef*mv.w;
            }
        }
    }
    float dinv = 1.f / denom;

    unsigned* yh = (unsigned*)(g_yah + (size_t)tok*DD + h*DKV + vq*32);
    const float* bet = betas + h*DKV + vq*32;
    #pragma unroll
    for (int u = 0; u < 8; u++){
        float4 o;
        float g0 = 1.f/(1.f + __expf(-bet[u*4+0]));
        float g1 = 1.f/(1.f + __expf(-bet[u*4+1]));
        float g2 = 1.f/(1.f + __expf(-bet[u*4+2]));
        float g3 = 1.f/(1.f + __expf(-bet[u*4+3]));
        o.x = g0*(accm[u].x*dinv) + (1.f - g0)*(accd[u].x*linv);
        o.y = g1*(accm[u].y*dinv) + (1.f - g1)*(accd[u].y*linv);
        o.z = g2*(accm[u].z*dinv) + (1.f - g2)*(accd[u].z*linv);
        o.w = g3*(accm[u].w*dinv) + (1.f - g3)*(accd[u].w*linv);
        yh[u*2]   = pack2h(o.x, o.y);
        yh[u*2+1] = pack2h(o.z, o.w);
    }
}

__global__ __launch_bounds__(256) void k_ln(const float* __restrict__ x,
                                            const float* __restrict__ lw, const float* __restrict__ lb,
                                            float* __restrict__ out, float* __restrict__ maskout)
{
    __shared__ float red[8];
    int token = blockIdx.x;
    int tid = threadIdx.x;
    int b = token >> 13;
    int p = g_pos[token];
    const float4* xp = (const float4*)(x + (size_t)token*DD);
    float4 v0 = xp[tid], v1 = xp[tid + 256];
    if (p >= 0){
        const float4* yp = (const float4*)(g_yfin + (size_t)(b*RL + p)*DD);
        float4 a = yp[tid], c = yp[tid + 256];
        v0.x += a.x; v0.y += a.y; v0.z += a.z; v0.w += a.w;
        v1.x += c.x; v1.y += c.y; v1.z += c.z; v1.w += c.w;
    }
    float sm = v0.x+v0.y+v0.z+v0.w + v1.x+v1.y+v1.z+v1.w;
    #pragma unroll
    for (int o = 16; o; o >>= 1) sm += __shfl_xor_sync(0xFFFFFFFFu, sm, o);
    int w = tid >> 5, lane = tid & 31;
    if (lane == 0) red[w] = sm;
    __syncthreads();
    float tot = 0.f;
    #pragma unroll
    for (int u = 0; u < 8; u++) tot += red[u];
    float mu = tot * (1.f/2048.f);
    __syncthreads();
    float d0 = v0.x-mu, d1 = v0.y-mu, d2 = v0.z-mu, d3 = v0.w-mu;
    float d4 = v1.x-mu, d5 = v1.y-mu, d6 = v1.z-mu, d7 = v1.w-mu;
    float sq = d0*d0+d1*d1+d2*d2+d3*d3+d4*d4+d5*d5+d6*d6+d7*d7;
    #pragma unroll
    for (int o = 16; o; o >>= 1) sq += __shfl_xor_sync(0xFFFFFFFFu, sq, o);
    if (lane == 0) red[w] = sq;
    __syncthreads();
    float tot2 = 0.f;
    #pragma unroll
    for (int u = 0; u < 8; u++) tot2 += red[u];
    float rstd = rsqrtf(tot2 * (1.f/2048.f) + 1e-5f);
    float4 w0 = ((const float4*)lw)[tid], w1_ = ((const float4*)lw)[tid + 256];
    float4 bb0 = ((const float4*)lb)[tid], bb1 = ((const float4*)lb)[tid + 256];
    float4 o0, o1;
    o0.x = d0*rstd*w0.x + bb0.x;  o0.y = d1*rstd*w0.y + bb0.y;
    o0.z = d2*rstd*w0.z + bb0.z;  o0.w = d3*rstd*w0.w + bb0.w;
    o1.x = d4*rstd*w1_.x + bb1.x; o1.y = d5*rstd*w1_.y + bb1.y;
    o1.z = d6*rstd*w1_.z + bb1.z; o1.w = d7*rstd*w1_.w + bb1.w;
    ((float4*)(out + (size_t)token*DD))[tid]       = o0;
    ((float4*)(out + (size_t)token*DD))[tid + 256] = o1;
    if (tid == 0) maskout[token] = (p >= 0) ? 1.f : 0.f;
}

extern "C" void kernel_launch(void* const* d_in, const int* in_sizes, int n_in,
                              void* d_out, int out_size)
{
    const float* x     = (const float*)d_in[0];
    const float* wq    = (const float*)d_in[1];
    const float* wk    = (const float*)d_in[2];
    const float* wv    = (const float*)d_in[3];
    const float* betas = (const float*)d_in[4];
    const float* wo    = (const float*)d_in[5];
    const float* w1    = (const float*)d_in[6];
    const float* b1    = (const float*)d_in[7];
    const float* w2    = (const float*)d_in[8];
    const float* b2    = (const float*)d_in[9];
    const float* lnw   = (const float*)d_in[10];
    const float* lnb   = (const float*)d_in[11];
    const float* wsamp = (const float*)d_in[12];
    const float* bsamp = (const float*)d_in[13];
    float* out = (float*)d_out;
    float* maskout = out + MASK_OFF;
    float* scout   = out + SC_OFF;

    static int cfg = 0;
    if (!cfg){
        cudaFuncSetAttribute(k_gemm_mma, cudaFuncAttributeMaxDynamicSharedMemorySize, GEMM_SMEM);
        cfg = 1;
    }

    #define SYM(T, p, s) T p; cudaGetSymbolAddress((void**)&p, s)
    SYM(float*, pyf, g_yfin);
    SYM(__half*, pxh, g_xh);
    SYM(__half*, pqh, g_qh); SYM(__half*, pkh, g_kh); SYM(__half*, pvh, g_vh);
    SYM(__half*, pyah, g_yah);
    SYM(__half*, py2h, g_y2h);
    SYM(__half*, phh, g_hh);
    SYM(__half*, pwqh, g_wqh);
    SYM(__half*, pwkh, g_wkh);
    SYM(__half*, pwvh, g_wvh);
    SYM(__half*, pwoh, g_woh);
    SYM(__half*, pw1h, g_w1h);
    SYM(__half*, pw2h, g_w2h);
    #undef SYM

    k_scores<<<BB*SS_/8, 256>>>(x, wsamp, bsamp, scout);
    k_topk<<<BB*NSF, 1024>>>(scout);
    k_gather<<<NT, 256>>>(x);
    k_cvt_h<<<(DD*DD/4+255)/256, 256>>>(wq, pwqh, DD*DD/4);

    dim3 g1(DD/128, NT/128, 1);
    k_gemm_mma<<<g1, 256, GEMM_SMEM>>>(pxh, pwqh, nullptr, nullptr, nullptr,
                                       pqh, nullptr, NT, DD, DD, 8);

    k_cvt_h<<<(DD*DD/4+255)/256, 256>>>(wk, pwkh, DD*DD/4);
    k_cvt_h<<<(DD*DD/4+255)/256, 256>>>(wv, pwvh, DD*DD/4);
    dim3 gkv(DD/128, NT/128, 2);
    k_gemm_mma<<<gkv, 256, GEMM_SMEM>>>(pxh, pwkh, pwvh, nullptr, nullptr,
                                        pkh, pvh, NT, DD, DD, 8);

    k_cvt_h<<<(DD*DD/4+255)/256, 256>>>(wo, pwoh, DD*DD/4);
    k_cvt_h<<<(DD*DHID/4+255)/256, 256>>>(w1, pw1h, DD*DHID/4);
    k_cvt_h<<<(DHID*DD/4+255)/256, 256>>>(w2, pw2h, DHID*DD/4);

    k_dmem<<<BB*HH*NSEG, 256>>>();
    k_zmpref<<<BB*HH, 256>>>();

    dim3 ga(BB*HH*NSEG, 4);
    k_attn<<<ga, 256>>>(betas);

    k_gemm_mma<<<g1, 256, GEMM_SMEM>>>(pyah, pwoh, nullptr, nullptr, nullptr,
                                       py2h, nullptr, NT, DD, DD, 8);
    dim3 g2(DHID/128, NT/128, 1);
    k_gemm_mma<<<g2, 256, GEMM_SMEM>>>(py2h, pw1h, nullptr, b1, nullptr,
                                       phh, nullptr, NT, DHID, DD, 11);
    k_gemm_mma<<<g1, 256, GEMM_SMEM>>>(phh, pw2h, nullptr, b2, pyf,
                                       nullptr, nullptr, NT, DD, DHID, 5);

    k_ln<<<BB*SS_, 256>>>(x, lnw, lnb, out, maskout);
}